// round 5
// baseline (speedup 1.0000x reference)
#include <cuda_runtime.h>
#include <cuda_bf16.h>
#include <math.h>
#include <stdint.h>

// Problem constants
#define BATCH 4
#define SEQ   4096
#define DIM   128
#define TOK   (BATCH*SEQ)   // 16384

// GEMM tiling
#define BM 128
#define BN 128
#define PADK 132    // fp32 smem row pitch for proj (floats)
#define SB   136    // bf16 smem row pitch (272 B -> ldmatrix conflict-free)

// ---------------- device scratch (allocation-free: __device__ globals) -------
__device__ __nv_bfloat16 g_Qh[TOK*DIM];   // Q in bf16
__device__ __nv_bfloat16 g_Kh[TOK*DIM];   // K in bf16
__device__ float g_V[TOK*DIM];            // V fp32
__device__ float g_C[BATCH*SEQ];          // column weights (already /N)

// ---------------- helpers ----------------------------------------------------
__device__ __forceinline__ float tf32_round(float x) {
    uint32_t u;
    asm("cvt.rna.tf32.f32 %0, %1;" : "=r"(u) : "f"(x));
    return __uint_as_float(u);
}

#define MMA_TF32(C, A, B)                                                     \
  asm volatile("mma.sync.aligned.m16n8k8.row.col.f32.tf32.tf32.f32 "          \
    "{%0,%1,%2,%3}, {%4,%5,%6,%7}, {%8,%9}, {%0,%1,%2,%3};"                   \
    : "+f"((C)[0]), "+f"((C)[1]), "+f"((C)[2]), "+f"((C)[3])                  \
    : "r"((A)[0]), "r"((A)[1]), "r"((A)[2]), "r"((A)[3]),                     \
      "r"((B)[0]), "r"((B)[1]))

#define MMA_BF16(C, A, B0, B1)                                                \
  asm volatile("mma.sync.aligned.m16n8k16.row.col.f32.bf16.bf16.f32 "         \
    "{%0,%1,%2,%3}, {%4,%5,%6,%7}, {%8,%9}, {%0,%1,%2,%3};"                   \
    : "+f"((C)[0]), "+f"((C)[1]), "+f"((C)[2]), "+f"((C)[3])                  \
    : "r"((A)[0]), "r"((A)[1]), "r"((A)[2]), "r"((A)[3]),                     \
      "r"(B0), "r"(B1))

#define LDMX4(R, ADDR)                                                        \
  asm volatile("ldmatrix.sync.aligned.m8n8.x4.shared.b16 {%0,%1,%2,%3}, [%4];"\
    : "=r"((R)[0]), "=r"((R)[1]), "=r"((R)[2]), "=r"((R)[3]) : "r"(ADDR))

#define CP_ASYNC16(dst, src)                                                  \
  asm volatile("cp.async.cg.shared.global [%0], [%1], 16;" :: "r"(dst), "l"(src))
#define CP_COMMIT() asm volatile("cp.async.commit_group;")
#define CP_WAIT1()  asm volatile("cp.async.wait_group 1;")
#define CP_WAIT0()  asm volatile("cp.async.wait_group 0;")

// ---------------- zero accumulators + output --------------------------------
__global__ void zero_kernel(float* out) {
    int i = blockIdx.x * blockDim.x + threadIdx.x;
    if (i < BATCH*SEQ) g_C[i] = 0.0f;
    if (i < BATCH*DIM) out[i] = 0.0f;
}

// ---------------- K1: QKV projection  y = x @ W^T + b  (tf32 mma) ------------
__global__ __launch_bounds__(256, 1)
void proj_kernel(const float* __restrict__ x,
                 const float* __restrict__ Wq, const float* __restrict__ bq,
                 const float* __restrict__ Wk, const float* __restrict__ bk,
                 const float* __restrict__ Wv, const float* __restrict__ bv) {
    extern __shared__ float sm[];
    float* As = sm;              // [BM][PADK]
    float* Bs = sm + BM*PADK;    // [BN][PADK]

    const float* W; const float* bias;
    if (blockIdx.z == 0)      { W = Wq; bias = bq; }
    else if (blockIdx.z == 1) { W = Wk; bias = bk; }
    else                      { W = Wv; bias = bv; }

    const int rowBase = blockIdx.y * BM;
    const int tid = threadIdx.x;

    for (int i = tid*4; i < BM*DIM; i += 256*4) {
        int r = i >> 7, k = i & 127;
        float4 v = *(const float4*)(x + (size_t)(rowBase + r)*DIM + k);
        v.x = tf32_round(v.x); v.y = tf32_round(v.y);
        v.z = tf32_round(v.z); v.w = tf32_round(v.w);
        *(float4*)(As + r*PADK + k) = v;
        float4 w = *(const float4*)(W + i);
        w.x = tf32_round(w.x); w.y = tf32_round(w.y);
        w.z = tf32_round(w.z); w.w = tf32_round(w.w);
        *(float4*)(Bs + r*PADK + k) = w;
    }
    __syncthreads();

    const int lane = tid & 31, warp = tid >> 5;
    const int wm = (warp >> 1) * 32;
    const int wn = (warp & 1) * 64;
    const int g = lane >> 2, t = lane & 3;

    float c[2][8][4];
    #pragma unroll
    for (int mt = 0; mt < 2; mt++)
        #pragma unroll
        for (int nt = 0; nt < 8; nt++)
            #pragma unroll
            for (int j = 0; j < 4; j++) c[mt][nt][j] = 0.0f;

    #pragma unroll
    for (int kk = 0; kk < DIM/8; kk++) {
        const int kb = kk*8;
        uint32_t a[2][4], bb[8][2];
        #pragma unroll
        for (int mt = 0; mt < 2; mt++) {
            const float* p = As + (wm + mt*16 + g)*PADK + kb + t;
            a[mt][0] = __float_as_uint(p[0]);
            a[mt][1] = __float_as_uint(p[8*PADK]);
            a[mt][2] = __float_as_uint(p[4]);
            a[mt][3] = __float_as_uint(p[8*PADK + 4]);
        }
        #pragma unroll
        for (int nt = 0; nt < 8; nt++) {
            const float* p = Bs + (wn + nt*8 + g)*PADK + kb + t;
            bb[nt][0] = __float_as_uint(p[0]);
            bb[nt][1] = __float_as_uint(p[4]);
        }
        #pragma unroll
        for (int mt = 0; mt < 2; mt++)
            #pragma unroll
            for (int nt = 0; nt < 8; nt++)
                MMA_TF32(c[mt][nt], a[mt], bb[nt]);
    }

    const bool isQK = (blockIdx.z < 2);
    __nv_bfloat16* oh = (blockIdx.z == 0) ? g_Qh : g_Kh;
    #pragma unroll
    for (int mt = 0; mt < 2; mt++) {
        const int r0 = rowBase + wm + mt*16 + g;
        #pragma unroll
        for (int nt = 0; nt < 8; nt++) {
            const int cn = wn + nt*8 + 2*t;
            float b0 = __ldg(&bias[cn]), b1 = __ldg(&bias[cn+1]);
            float v00 = c[mt][nt][0] + b0, v01 = c[mt][nt][1] + b1;
            float v10 = c[mt][nt][2] + b0, v11 = c[mt][nt][3] + b1;
            if (isQK) {
                *(__nv_bfloat162*)(oh + (size_t)r0*DIM + cn)     = __floats2bfloat162_rn(v00, v01);
                *(__nv_bfloat162*)(oh + (size_t)(r0+8)*DIM + cn) = __floats2bfloat162_rn(v10, v11);
            } else {
                *(float2*)(g_V + (size_t)r0*DIM + cn)     = make_float2(v00, v01);
                *(float2*)(g_V + (size_t)(r0+8)*DIM + cn) = make_float2(v10, v11);
            }
        }
    }
}

// ---------------- K2: fused two-pass attention column weights ----------------
// Block = (batch b, 128 query rows). Pass 1: S[row] = sum_m exp(s).
// Pass 2: colAcc[m] += exp(s)/S[row], accumulated in smem, flushed to g_C.
__global__ __launch_bounds__(256, 1)
void attn_kernel() {
    extern __shared__ float smf[];
    float* colAcc = smf;                    // [SEQ]
    float* Ssm    = smf + SEQ;              // [BM]
    __nv_bfloat16* Qs = (__nv_bfloat16*)(smf + SEQ + BM);   // [BM][SB]
    __nv_bfloat16* Ks = Qs + BM*SB;                          // 2 x [BN][SB]

    const int b = blockIdx.y;
    const int rowBase = blockIdx.x * BM;
    const int tid = threadIdx.x;

    for (int i = tid; i < SEQ; i += 256) colAcc[i] = 0.0f;
    if (tid < BM) Ssm[tid] = 0.0f;

    // load Q tile (loop-invariant)
    {
        const uint4* Qg = (const uint4*)(g_Qh + ((size_t)b*SEQ + rowBase)*DIM);
        #pragma unroll
        for (int j = 0; j < 8; j++) {
            int i = tid + j*256;
            int r = i >> 4, ch = i & 15;
            *(uint4*)(Qs + r*SB + ch*8) = Qg[r*16 + ch];
        }
    }
    __syncthreads();

    const int lane = tid & 31, warp = tid >> 5;
    const int wm = (warp >> 1) * 32;
    const int wn = (warp & 1) * 64;
    const int g = lane >> 2, qt = lane & 3;

    // hoisted A fragments (Q) for all 8 k-chunks
    uint32_t aF[8][2][4];
    {
        const int aRow = wm + (lane & 15);
        const int aCol = (lane >> 4) << 3;
        uint32_t aAddr = (uint32_t)__cvta_generic_to_shared(Qs + aRow*SB + aCol);
        #pragma unroll
        for (int kk = 0; kk < 8; kk++)
            #pragma unroll
            for (int mt = 0; mt < 2; mt++)
                LDMX4(aF[kk][mt], aAddr + (mt*16*SB)*2 + kk*32);
    }

    const int bRow = wn + (lane & 7) + ((lane >> 4) << 3);
    const int bCol = ((lane >> 3) & 1) << 3;
    uint32_t bAddrBase[2];
    bAddrBase[0] = (uint32_t)__cvta_generic_to_shared(Ks + bRow*SB + bCol);
    bAddrBase[1] = (uint32_t)__cvta_generic_to_shared(Ks + BM*SB + bRow*SB + bCol);

    const __nv_bfloat16* Kbase = g_Kh + (size_t)b*SEQ*DIM;

    // per-thread K-tile prefetch addressing
    const int pr = tid >> 4;          // rows pr, pr+16, ... pr+112 (8 chunks stride 256 threads)
    const int pch = tid & 15;

    float rs[4] = {0.f, 0.f, 0.f, 0.f};
    float is[4] = {0.f, 0.f, 0.f, 0.f};

    #pragma unroll 1
    for (int pass = 0; pass < 2; pass++) {
        // prefetch tile 0 into buf 0
        #pragma unroll
        for (int j = 0; j < 8; j++) {
            int r = pr + j*16;
            uint32_t dst = (uint32_t)__cvta_generic_to_shared(Ks + r*SB + pch*8);
            const void* src = Kbase + (size_t)r*DIM + pch*8;
            CP_ASYNC16(dst, src);
        }
        CP_COMMIT();

        #pragma unroll 1
        for (int kt = 0; kt < 32; kt++) {
            __syncthreads();   // all warps done with buffer being overwritten next
            if (kt + 1 < 32) {
                const __nv_bfloat16* src0 = Kbase + (size_t)(kt+1)*BN*DIM;
                __nv_bfloat16* dstb = Ks + ((kt+1)&1)*BM*SB;
                #pragma unroll
                for (int j = 0; j < 8; j++) {
                    int r = pr + j*16;
                    uint32_t dst = (uint32_t)__cvta_generic_to_shared(dstb + r*SB + pch*8);
                    CP_ASYNC16(dst, src0 + (size_t)r*DIM + pch*8);
                }
                CP_COMMIT();
                CP_WAIT1();
            } else {
                CP_WAIT0();
            }
            __syncthreads();   // tile kt visible to all warps

            const uint32_t bAddr = bAddrBase[kt & 1];
            float c[2][8][4];
            #pragma unroll
            for (int mt = 0; mt < 2; mt++)
                #pragma unroll
                for (int nt = 0; nt < 8; nt++)
                    #pragma unroll
                    for (int j = 0; j < 4; j++) c[mt][nt][j] = 0.0f;

            #pragma unroll
            for (int kk = 0; kk < 8; kk++) {
                uint32_t bb[4][4];
                #pragma unroll
                for (int ntp = 0; ntp < 4; ntp++)
                    LDMX4(bb[ntp], bAddr + (ntp*16*SB)*2 + kk*32);
                #pragma unroll
                for (int mt = 0; mt < 2; mt++)
                    #pragma unroll
                    for (int nt = 0; nt < 8; nt++)
                        MMA_BF16(c[mt][nt], aF[kk][mt],
                                 bb[nt>>1][(nt&1)*2], bb[nt>>1][(nt&1)*2+1]);
            }

            if (pass == 0) {
                #pragma unroll
                for (int mt = 0; mt < 2; mt++)
                    #pragma unroll
                    for (int nt = 0; nt < 8; nt++) {
                        rs[mt*2]   += __expf(c[mt][nt][0]) + __expf(c[mt][nt][1]);
                        rs[mt*2+1] += __expf(c[mt][nt][2]) + __expf(c[mt][nt][3]);
                    }
            } else {
                const int colBase = kt*BN + wn;
                #pragma unroll
                for (int nt = 0; nt < 8; nt++) {
                    float s0 = 0.0f, s1 = 0.0f;
                    #pragma unroll
                    for (int mt = 0; mt < 2; mt++) {
                        s0 += __expf(c[mt][nt][0])*is[mt*2] + __expf(c[mt][nt][2])*is[mt*2+1];
                        s1 += __expf(c[mt][nt][1])*is[mt*2] + __expf(c[mt][nt][3])*is[mt*2+1];
                    }
                    // reduce over the 8 g-lanes (rows)
                    #pragma unroll
                    for (int o = 4; o <= 16; o <<= 1) {
                        s0 += __shfl_xor_sync(0xffffffffu, s0, o);
                        s1 += __shfl_xor_sync(0xffffffffu, s1, o);
                    }
                    if (lane < 4) {
                        atomicAdd(&colAcc[colBase + nt*8 + 2*lane],     s0);
                        atomicAdd(&colAcc[colBase + nt*8 + 2*lane + 1], s1);
                    }
                }
            }
        }

        if (pass == 0) {
            // finalize row sums -> invS
            #pragma unroll
            for (int i = 0; i < 4; i++) {
                rs[i] += __shfl_xor_sync(0xffffffffu, rs[i], 1);
                rs[i] += __shfl_xor_sync(0xffffffffu, rs[i], 2);
            }
            if (qt == 0) {
                #pragma unroll
                for (int i = 0; i < 4; i++)
                    atomicAdd(&Ssm[wm + (i>>1)*16 + (i&1)*8 + g], rs[i]);
            }
            __syncthreads();
            if (tid < BM) Ssm[tid] = 1.0f / Ssm[tid];
            __syncthreads();
            #pragma unroll
            for (int i = 0; i < 4; i++)
                is[i] = Ssm[wm + (i>>1)*16 + (i&1)*8 + g];
        }
    }

    __syncthreads();
    for (int i = tid; i < SEQ; i += 256)
        atomicAdd(&g_C[b*SEQ + i], colAcc[i] * (1.0f/SEQ));
}

// ---------------- K4: out[b,d] = sum_m c[m] * V[b,m,d] -----------------------
#define K4_CHUNK (SEQ/16)   // 256 rows per block
__global__ __launch_bounds__(128, 8)
void out_kernel(float* __restrict__ out) {
    const int b = blockIdx.y;
    const int mBase = blockIdx.x * K4_CHUNK;
    const int d = threadIdx.x;
    const float* Vp = g_V + ((size_t)b*SEQ + mBase)*DIM + d;
    const float* Cp = g_C + b*SEQ + mBase;
    float acc = 0.0f;
    #pragma unroll 8
    for (int m = 0; m < K4_CHUNK; m++)
        acc += Cp[m] * Vp[(size_t)m*DIM];
    atomicAdd(&out[b*DIM + d], acc);
}

// ---------------- launch -----------------------------------------------------
extern "C" void kernel_launch(void* const* d_in, const int* in_sizes, int n_in,
                              void* d_out, int out_size) {
    const float* x  = (const float*)d_in[0];
    const float* Wq = (const float*)d_in[1];
    const float* bq = (const float*)d_in[2];
    const float* Wk = (const float*)d_in[3];
    const float* bk = (const float*)d_in[4];
    const float* Wv = (const float*)d_in[5];
    const float* bv = (const float*)d_in[6];
    float* out = (float*)d_out;

    const int smemProj = 2 * BM * PADK * sizeof(float);                       // 135168 B
    const int smemAttn = (SEQ + BM) * sizeof(float) + 3 * BM * SB * 2;        // 121344 B
    cudaFuncSetAttribute(proj_kernel, cudaFuncAttributeMaxDynamicSharedMemorySize, smemProj);
    cudaFuncSetAttribute(attn_kernel, cudaFuncAttributeMaxDynamicSharedMemorySize, smemAttn);

    zero_kernel<<<(BATCH*SEQ + 255)/256, 256>>>(out);

    dim3 gProj(1, TOK/BM, 3);
    proj_kernel<<<gProj, 256, smemProj>>>(x, Wq, bq, Wk, bk, Wv, bv);

    dim3 gAttn(SEQ/BM, BATCH);   // 32 x 4 = 128 blocks
    attn_kernel<<<gAttn, 256, smemAttn>>>();

    dim3 gOut(16, BATCH);
    out_kernel<<<gOut, 128>>>(out);
}

// round 7
// speedup vs baseline: 1.4984x; 1.4984x over previous
#include <cuda_runtime.h>
#include <cuda_bf16.h>
#include <math.h>
#include <stdint.h>

// Problem constants
#define BATCH 4
#define SEQ   4096
#define DIM   128
#define TOK   (BATCH*SEQ)   // 16384

#define BM 128
#define BN 128
#define PADK 132    // fp32 smem row pitch for proj (floats); 528B rows, 16B aligned
#define SB   136    // bf16 smem row pitch for score (272 B)
#define LOG2E 1.4426950408889634f

// ---------------- device scratch (allocation-free: __device__ globals) -------
__device__ __nv_bfloat16 g_Qh[TOK*DIM];                // Q' = log2e * Q, bf16
__device__ __nv_bfloat16 g_Kh[TOK*DIM];                // K, bf16
__device__ float g_V[TOK*DIM];                         // V fp32
__device__ float g_S[BATCH*SEQ];                       // row sums of 2^(s')
__device__ float g_C[BATCH*SEQ];                       // column weights
__device__ __nv_bfloat16 g_E[(size_t)BATCH*SEQ*SEQ];   // 2^(s'), bf16, 134 MB

// ---------------- helpers ----------------------------------------------------
__device__ __forceinline__ float ex2f(float x) {
    float y; asm("ex2.approx.f32 %0, %1;" : "=f"(y) : "f"(x)); return y;
}

#define MMA_TF32(C, A, B)                                                     \
  asm volatile("mma.sync.aligned.m16n8k8.row.col.f32.tf32.tf32.f32 "          \
    "{%0,%1,%2,%3}, {%4,%5,%6,%7}, {%8,%9}, {%0,%1,%2,%3};"                   \
    : "+f"((C)[0]), "+f"((C)[1]), "+f"((C)[2]), "+f"((C)[3])                  \
    : "r"((A)[0]), "r"((A)[1]), "r"((A)[2]), "r"((A)[3]),                     \
      "r"((B)[0]), "r"((B)[1]))

#define MMA_BF16(C, A, B0, B1)                                                \
  asm volatile("mma.sync.aligned.m16n8k16.row.col.f32.bf16.bf16.f32 "         \
    "{%0,%1,%2,%3}, {%4,%5,%6,%7}, {%8,%9}, {%0,%1,%2,%3};"                   \
    : "+f"((C)[0]), "+f"((C)[1]), "+f"((C)[2]), "+f"((C)[3])                  \
    : "r"((A)[0]), "r"((A)[1]), "r"((A)[2]), "r"((A)[3]),                     \
      "r"(B0), "r"(B1))

#define LDMX4(R, ADDR)                                                        \
  asm volatile("ldmatrix.sync.aligned.m8n8.x4.shared.b16 {%0,%1,%2,%3}, [%4];"\
    : "=r"((R)[0]), "=r"((R)[1]), "=r"((R)[2]), "=r"((R)[3]) : "r"(ADDR))

#define CP_ASYNC16(dst, src)                                                  \
  asm volatile("cp.async.cg.shared.global [%0], [%1], 16;" :: "r"(dst), "l"(src))
#define CP_COMMIT() asm volatile("cp.async.commit_group;")
#define CP_WAIT1()  asm volatile("cp.async.wait_group 1;")
#define CP_WAIT0()  asm volatile("cp.async.wait_group 0;")

// ---------------- zero accumulators + output --------------------------------
__global__ void zero_kernel(float* out) {
    int i = blockIdx.x * blockDim.x + threadIdx.x;
    if (i < BATCH*SEQ) { g_S[i] = 0.0f; g_C[i] = 0.0f; }
    if (i < BATCH*DIM) out[i] = 0.0f;
}

// ---------------- K1: QKV projection, z-loop + double-buffered W -------------
// 128 blocks; each computes Q,K,V for its 128 rows. x loaded once.
// NOTE: 128x128 fp32 tile = 4096 16B-chunks -> 16 chunks per thread (j<16).
__global__ __launch_bounds__(256, 1)
void proj_kernel(const float* __restrict__ x,
                 const float* __restrict__ Wq, const float* __restrict__ bq,
                 const float* __restrict__ Wk, const float* __restrict__ bk,
                 const float* __restrict__ Wv, const float* __restrict__ bv) {
    extern __shared__ float sm[];
    float* As = sm;                   // [BM][PADK]
    float* Wb[2] = { sm + BM*PADK, sm + 2*BM*PADK };

    const int rowBase = blockIdx.x * BM;
    const int tid = threadIdx.x;

    // group 0: As (x tile) + W0 (Wq)
    #pragma unroll
    for (int j = 0; j < 16; j++) {
        int c = tid + j*256;          // 4096 chunks of 16B
        int r = c >> 5, k4 = (c & 31) * 4;
        CP_ASYNC16((uint32_t)__cvta_generic_to_shared(As + r*PADK + k4),
                   x + (size_t)(rowBase + r)*DIM + k4);
        CP_ASYNC16((uint32_t)__cvta_generic_to_shared(Wb[0] + r*PADK + k4),
                   Wq + r*DIM + k4);
    }
    CP_COMMIT();
    // group 1: W1 (Wk)
    #pragma unroll
    for (int j = 0; j < 16; j++) {
        int c = tid + j*256;
        int r = c >> 5, k4 = (c & 31) * 4;
        CP_ASYNC16((uint32_t)__cvta_generic_to_shared(Wb[1] + r*PADK + k4),
                   Wk + r*DIM + k4);
    }
    CP_COMMIT();
    CP_WAIT1();   // As + W0 arrived
    __syncthreads();

    const int lane = tid & 31, warp = tid >> 5;
    const int wm = (warp >> 1) * 32;
    const int wn = (warp & 1) * 64;
    const int g = lane >> 2, t = lane & 3;

    #pragma unroll 1
    for (int z = 0; z < 3; z++) {
        float* Bs = Wb[z == 1];                       // z=0->W0, z=1->W1, z=2->W0
        const float* bias = (z == 0) ? bq : (z == 1) ? bk : bv;

        float c[2][8][4];
        #pragma unroll
        for (int mt = 0; mt < 2; mt++)
            #pragma unroll
            for (int nt = 0; nt < 8; nt++)
                #pragma unroll
                for (int j = 0; j < 4; j++) c[mt][nt][j] = 0.0f;

        // mma.tf32 truncates fp32 operands to tf32 in HW — no pre-rounding pass.
        #pragma unroll
        for (int kk = 0; kk < DIM/8; kk++) {
            const int kb = kk*8;
            uint32_t a[2][4], bb[8][2];
            #pragma unroll
            for (int mt = 0; mt < 2; mt++) {
                const float* p = As + (wm + mt*16 + g)*PADK + kb + t;
                a[mt][0] = __float_as_uint(p[0]);
                a[mt][1] = __float_as_uint(p[8*PADK]);
                a[mt][2] = __float_as_uint(p[4]);
                a[mt][3] = __float_as_uint(p[8*PADK + 4]);
            }
            #pragma unroll
            for (int nt = 0; nt < 8; nt++) {
                const float* p = Bs + (wn + nt*8 + g)*PADK + kb + t;
                bb[nt][0] = __float_as_uint(p[0]);
                bb[nt][1] = __float_as_uint(p[4]);
            }
            #pragma unroll
            for (int mt = 0; mt < 2; mt++)
                #pragma unroll
                for (int nt = 0; nt < 8; nt++)
                    MMA_TF32(c[mt][nt], a[mt], bb[nt]);
        }

        // epilogue: bias (+ log2e scale for Q), store
        const float scale = (z == 0) ? LOG2E : 1.0f;
        __nv_bfloat16* oh = (z == 0) ? g_Qh : g_Kh;
        #pragma unroll
        for (int mt = 0; mt < 2; mt++) {
            const int r0 = rowBase + wm + mt*16 + g;
            #pragma unroll
            for (int nt = 0; nt < 8; nt++) {
                const int cn = wn + nt*8 + 2*t;
                float b0 = __ldg(&bias[cn]), b1 = __ldg(&bias[cn+1]);
                float v00 = (c[mt][nt][0] + b0) * scale, v01 = (c[mt][nt][1] + b1) * scale;
                float v10 = (c[mt][nt][2] + b0) * scale, v11 = (c[mt][nt][3] + b1) * scale;
                if (z < 2) {
                    *(__nv_bfloat162*)(oh + (size_t)r0*DIM + cn)     = __floats2bfloat162_rn(v00, v01);
                    *(__nv_bfloat162*)(oh + (size_t)(r0+8)*DIM + cn) = __floats2bfloat162_rn(v10, v11);
                } else {
                    *(float2*)(g_V + (size_t)r0*DIM + cn)     = make_float2(v00, v01);
                    *(float2*)(g_V + (size_t)(r0+8)*DIM + cn) = make_float2(v10, v11);
                }
            }
        }

        if (z == 0) {
            __syncthreads();                    // everyone done reading W0
            #pragma unroll
            for (int j = 0; j < 16; j++) {      // group 2: Wv into buf0
                int cc = tid + j*256;
                int r = cc >> 5, k4 = (cc & 31) * 4;
                CP_ASYNC16((uint32_t)__cvta_generic_to_shared(Wb[0] + r*PADK + k4),
                           Wv + r*DIM + k4);
            }
            CP_COMMIT();
            CP_WAIT1();                         // W1 (Wk) arrived
            __syncthreads();
        } else if (z == 1) {
            __syncthreads();
            CP_WAIT0();                         // Wv arrived
            __syncthreads();
        }
    }
}

// ---------------- K2: E = 2^(Q' K^T) (bf16 mma + ldmatrix), rowsums ----------
__global__ __launch_bounds__(256, 2)
void score_kernel() {
    extern __shared__ __nv_bfloat16 smh[];
    __nv_bfloat16* Qs = smh;            // [BM][SB]
    __nv_bfloat16* Ks = smh + BM*SB;    // [BN][SB]

    const int b = blockIdx.z;
    const int rowBase = blockIdx.y * BM;
    const int colBase = blockIdx.x * BN;
    const int tid = threadIdx.x;

    {
        const uint4* Qg = (const uint4*)(g_Qh + ((size_t)b*SEQ + rowBase)*DIM);
        const uint4* Kg = (const uint4*)(g_Kh + ((size_t)b*SEQ + colBase)*DIM);
        #pragma unroll
        for (int i = tid; i < BM*16; i += 256) {
            int r = i >> 4, ch = i & 15;
            *(uint4*)(Qs + r*SB + ch*8) = Qg[r*16 + ch];
            *(uint4*)(Ks + r*SB + ch*8) = Kg[r*16 + ch];
        }
    }
    __syncthreads();

    const int lane = tid & 31, warp = tid >> 5;
    const int wm = (warp >> 1) * 32;
    const int wn = (warp & 1) * 64;

    const int aRow = wm + (lane & 15);
    const int aCol = (lane >> 4) << 3;
    uint32_t aAddr = (uint32_t)__cvta_generic_to_shared(Qs + aRow*SB + aCol);
    const int bRow = wn + (lane & 7) + ((lane >> 4) << 3);
    const int bCol = ((lane >> 3) & 1) << 3;
    uint32_t bAddr = (uint32_t)__cvta_generic_to_shared(Ks + bRow*SB + bCol);

    float c[2][8][4];
    #pragma unroll
    for (int mt = 0; mt < 2; mt++)
        #pragma unroll
        for (int nt = 0; nt < 8; nt++)
            #pragma unroll
            for (int j = 0; j < 4; j++) c[mt][nt][j] = 0.0f;

    #pragma unroll
    for (int kk = 0; kk < DIM/16; kk++) {
        uint32_t a[2][4], bb[4][4];
        #pragma unroll
        for (int mt = 0; mt < 2; mt++)
            LDMX4(a[mt], aAddr + (mt*16*SB)*2 + kk*32);
        #pragma unroll
        for (int ntp = 0; ntp < 4; ntp++)
            LDMX4(bb[ntp], bAddr + (ntp*16*SB)*2 + kk*32);
        #pragma unroll
        for (int mt = 0; mt < 2; mt++)
            #pragma unroll
            for (int nt = 0; nt < 8; nt++)
                MMA_BF16(c[mt][nt], a[mt], bb[nt>>1][(nt&1)*2], bb[nt>>1][(nt&1)*2+1]);
    }

    const int g = lane >> 2, t = lane & 3;
    #pragma unroll
    for (int mt = 0; mt < 2; mt++) {
        const int r0 = rowBase + wm + mt*16 + g;
        const int r1 = r0 + 8;
        float rs0 = 0.0f, rs1 = 0.0f;
        #pragma unroll
        for (int nt = 0; nt < 8; nt++) {
            const int cn = colBase + wn + nt*8 + 2*t;
            float e0 = ex2f(c[mt][nt][0]);
            float e1 = ex2f(c[mt][nt][1]);
            float e2 = ex2f(c[mt][nt][2]);
            float e3 = ex2f(c[mt][nt][3]);
            rs0 += e0 + e1;
            rs1 += e2 + e3;
            size_t base0 = ((size_t)b*SEQ + r0)*SEQ + cn;
            size_t base1 = ((size_t)b*SEQ + r1)*SEQ + cn;
            *(__nv_bfloat162*)(g_E + base0) = __floats2bfloat162_rn(e0, e1);
            *(__nv_bfloat162*)(g_E + base1) = __floats2bfloat162_rn(e2, e3);
        }
        #pragma unroll
        for (int o = 1; o <= 2; o <<= 1) {
            rs0 += __shfl_xor_sync(0xffffffffu, rs0, o);
            rs1 += __shfl_xor_sync(0xffffffffu, rs1, o);
        }
        if (t == 0) {
            atomicAdd(&g_S[b*SEQ + r0], rs0);
            atomicAdd(&g_S[b*SEQ + r1], rs1);
        }
    }
}

// ---------------- K3: row-major streaming colsum -----------------------------
// Block = (128 rows, all 4096 cols). Thread owns 8 columns in registers.
#define CS_ROWS 128
__global__ __launch_bounds__(512, 2)
void colsum_kernel() {
    __shared__ float invS[CS_ROWS];
    const int b = blockIdx.y;
    const int rBase = blockIdx.x * CS_ROWS;
    const int tid = threadIdx.x;

    if (tid < CS_ROWS) invS[tid] = 1.0f / g_S[b*SEQ + rBase + tid];
    __syncthreads();

    // row stride in uint4: SEQ bf16 = 8192 B = 512 uint4
    const uint4* Ep = (const uint4*)(g_E + ((size_t)b*SEQ + rBase)*SEQ) + tid;

    float acc[8];
    #pragma unroll
    for (int i = 0; i < 8; i++) acc[i] = 0.0f;

    #pragma unroll 2
    for (int r = 0; r < CS_ROWS; r += 2) {
        uint4 p0 = Ep[(size_t)r * 512];
        uint4 p1 = Ep[(size_t)(r+1) * 512];
        float w0 = invS[r], w1 = invS[r+1];
        const uint32_t u0[4] = {p0.x, p0.y, p0.z, p0.w};
        const uint32_t u1[4] = {p1.x, p1.y, p1.z, p1.w};
        #pragma unroll
        for (int k = 0; k < 4; k++) {
            acc[2*k]   += __uint_as_float(u0[k] << 16)          * w0
                        + __uint_as_float(u1[k] << 16)          * w1;
            acc[2*k+1] += __uint_as_float(u0[k] & 0xffff0000u)  * w0
                        + __uint_as_float(u1[k] & 0xffff0000u)  * w1;
        }
    }

    const int m = tid * 8;   // 512 threads * 8 = 4096 columns
    #pragma unroll
    for (int i = 0; i < 8; i++)
        atomicAdd(&g_C[b*SEQ + m + i], acc[i] * (1.0f/SEQ));
}

// ---------------- K4: out[b,d] = sum_m c[m] * V[b,m,d] -----------------------
__global__ __launch_bounds__(256, 4)
void out_kernel(float* __restrict__ out) {
    const int b = blockIdx.y;
    const int mBase = blockIdx.x * 128;
    const int d = threadIdx.x & 127;
    const int h = threadIdx.x >> 7;
    const float* Vp = g_V + ((size_t)b*SEQ + mBase + h)*DIM + d;
    const float* Cp = g_C + b*SEQ + mBase + h;
    float acc = 0.0f;
    #pragma unroll 8
    for (int m = 0; m < 128; m += 2)
        acc += Cp[m] * Vp[(size_t)m*DIM];
    atomicAdd(&out[b*DIM + d], acc);
}

// ---------------- launch -----------------------------------------------------
extern "C" void kernel_launch(void* const* d_in, const int* in_sizes, int n_in,
                              void* d_out, int out_size) {
    const float* x  = (const float*)d_in[0];
    const float* Wq = (const float*)d_in[1];
    const float* bq = (const float*)d_in[2];
    const float* Wk = (const float*)d_in[3];
    const float* bk = (const float*)d_in[4];
    const float* Wv = (const float*)d_in[5];
    const float* bv = (const float*)d_in[6];
    float* out = (float*)d_out;

    const int smemProj  = 3 * BM * PADK * sizeof(float);          // 202752 B
    const int smemScore = 2 * BM * SB * sizeof(__nv_bfloat16);    // 69632 B
    cudaFuncSetAttribute(proj_kernel,  cudaFuncAttributeMaxDynamicSharedMemorySize, smemProj);
    cudaFuncSetAttribute(score_kernel, cudaFuncAttributeMaxDynamicSharedMemorySize, smemScore);

    zero_kernel<<<(BATCH*SEQ + 255)/256, 256>>>(out);

    proj_kernel<<<TOK/BM, 256, smemProj>>>(x, Wq, bq, Wk, bk, Wv, bv);

    dim3 gScore(SEQ/BN, SEQ/BM, BATCH);   // 32 x 32 x 4
    score_kernel<<<gScore, 256, smemScore>>>();

    dim3 gCol(SEQ/CS_ROWS, BATCH);        // 32 x 4
    colsum_kernel<<<gCol, 512>>>();

    dim3 gOut(SEQ/128, BATCH);            // 32 x 4
    out_kernel<<<gOut, 256>>>(out);
}